// round 14
// baseline (speedup 1.0000x reference)
#include <cuda_runtime.h>
#include <cuda_fp16.h>

#define NMAX 100000
#define EMAX 1250000
#define F 64
#define GRID_P1 592            // 148 SMs x 4 blocks, all resident

// Scratch (__device__ globals; no allocation allowed)
__device__ int   g_deg[NMAX];
__device__ int   g_rowtmp[NMAX];
__device__ int   g_rowptr[NMAX];     // after fill: row END (start+deg)
__device__ float g_dinv[NMAX];
__device__ int   g_chunksum[256];
__device__ int   g_chunkoff[256];
__device__ int   g_barstate[2];      // {cnt, gen}; memset to 0 each call
__device__ int   g_csr[EMAX];
__device__ __align__(16) __half g_hsH [NMAX * F];  // layer-1 dinv-prescaled (fp16)
__device__ __align__(16) __half g_h1H [NMAX * F];  // relu(layer-1 out) (fp16)
__device__ __align__(16) __half g_hs2H[NMAX * F];  // layer-2 dinv-prescaled (fp16)
__device__ float g_gsum[F];

// sense-reversing grid barrier. ALL threads fence (release of their writes)
// before arrival; acquire fence after release-observe.
__device__ __forceinline__ void grid_barrier() {
    __threadfence();                 // release: order THIS thread's writes
    __syncthreads();
    if (threadIdx.x == 0) {
        volatile int* vgen = &g_barstate[1];
        int g = *vgen;
        if (atomicAdd(&g_barstate[0], 1) == (int)gridDim.x - 1) {
            *(volatile int*)&g_barstate[0] = 0;
            __threadfence();
            *vgen = g + 1;
        } else {
            while (*vgen == g) { }
            __threadfence();         // acquire
        }
    }
    __syncthreads();
}

// exclusive scan of `v` over 256 threads; returns exclusive prefix, total in *tot
__device__ __forceinline__ int block_excl_scan256(int v, int* smWarp, int* tot) {
    int lane = threadIdx.x & 31, wid = threadIdx.x >> 5;
    int x = v;
    #pragma unroll
    for (int off = 1; off < 32; off <<= 1) {
        int t = __shfl_up_sync(0xffffffffu, x, off);
        if (lane >= off) x += t;
    }
    if (lane == 31) smWarp[wid] = x;
    __syncthreads();
    if (wid == 0 && lane < 8) {
        int y = smWarp[lane];
        #pragma unroll
        for (int off = 1; off < 8; off <<= 1) {
            int t = __shfl_up_sync(0x000000ffu, y, off);
            if (lane >= off) y += t;
        }
        smWarp[lane] = y;
    }
    __syncthreads();
    int base = (wid > 0) ? smWarp[wid - 1] : 0;
    *tot = smWarp[7];
    __syncthreads();
    return base + x - v;
}

// ---------------------------------------------------------------------------
// Persistent graph-build kernel: deg -> scan -> dinv+GEMM1 -> CSR fill
__global__ void __launch_bounds__(256, 4)
k_build(const float* __restrict__ x, const float* __restrict__ W1,
        const int* __restrict__ src, const int* __restrict__ dst, int n, int e) {
    __shared__ float W1t[F][12];                   // W1t[j][k]
    __shared__ int smWarp[8];
    int tid = threadIdx.x;
    int gt = blockIdx.x * 256 + tid;
    int gstride = GRID_P1 * 256;                   // 151552 >= n

    // phase 0: zero deg (L2 store) + stage ALL 512 W1 elements (256 threads!)
    if (gt < n) __stcg(&g_deg[gt], 0);
    for (int t = tid; t < F * 8; t += 256) {
        int k = t >> 6, j = t & 63;
        W1t[j][k] = W1[t];
    }
    grid_barrier();

    // phase 1: in-degree count, 8-deep MLP (atomics live in L2)
    {
        int i = gt;
        for (; i + 7 * gstride < e; i += 8 * gstride) {
            int d[8];
            #pragma unroll
            for (int m = 0; m < 8; m++) d[m] = dst[i + m * gstride];
            #pragma unroll
            for (int m = 0; m < 8; m++) atomicAdd(&g_deg[d[m]], 1);
        }
        for (; i < e; i += gstride) atomicAdd(&g_deg[dst[i]], 1);
    }
    grid_barrier();

    // phase 2: per-512-chunk exclusive scan (block handles chunk = blockIdx.x)
    int nchunks = (n + 511) >> 9;                  // 196
    if ((int)blockIdx.x < nchunks) {
        int base = blockIdx.x << 9;
        int i0 = base + 2 * tid, i1 = i0 + 1;
        int v0 = (i0 < n) ? __ldcg(&g_deg[i0]) : 0;
        int v1 = (i1 < n) ? __ldcg(&g_deg[i1]) : 0;
        int tot;
        int excl = block_excl_scan256(v0 + v1, smWarp, &tot);
        if (i0 < n) __stcg(&g_rowtmp[i0], excl);
        if (i1 < n) __stcg(&g_rowtmp[i1], excl + v0);
        if (tid == 0) __stcg(&g_chunksum[blockIdx.x], tot);
    }
    grid_barrier();

    // phase 3: block 0 scans chunk sums (nchunks <= 256)
    if (blockIdx.x == 0) {
        int v = (tid < nchunks) ? __ldcg(&g_chunksum[tid]) : 0;
        int tot;
        int excl = block_excl_scan256(v, smWarp, &tot);
        if (tid < nchunks) __stcg(&g_chunkoff[tid], excl);
    }
    grid_barrier();

    // phase 4: rowptr = rowtmp + chunkoff ; dinv ; fused GEMM1 (fp16 out)
    if (gt < n) {
        int i = gt;
        __stcg(&g_rowptr[i], __ldcg(&g_rowtmp[i]) + __ldcg(&g_chunkoff[i >> 9]));
        int v = __ldcg(&g_deg[i]);
        float dinv = rsqrtf((float)(v + 1));
        g_dinv[i] = dinv;                          // consumed by later kernels
        float4 xa = ((const float4*)x)[i * 2];
        float4 xb = ((const float4*)x)[i * 2 + 1];
        #pragma unroll
        for (int c = 0; c < 8; c++) {
            union { uint4 u; __half2 h[4]; } pk;
            #pragma unroll
            for (int m = 0; m < 4; m++) {
                float s[2];
                #pragma unroll
                for (int t = 0; t < 2; t++) {
                    int j = 8 * c + 2 * m + t;
                    float4 wa = *(const float4*)&W1t[j][0];
                    float4 wb = *(const float4*)&W1t[j][4];
                    s[t] = (xa.x*wa.x + xa.y*wa.y + xa.z*wa.z + xa.w*wa.w
                          + xb.x*wb.x + xb.y*wb.y + xb.z*wb.z + xb.w*wb.w) * dinv;
                }
                pk.h[m] = __floats2half2_rn(s[0], s[1]);
            }
            ((uint4*)g_hsH)[(size_t)i * 8 + c] = pk.u;
        }
    }
    grid_barrier();

    // phase 5: CSR fill, 4-deep MLP
    {
        int i = gt;
        for (; i + 3 * gstride < e; i += 4 * gstride) {
            int d0 = dst[i],               d1 = dst[i + gstride];
            int d2 = dst[i + 2 * gstride], d3 = dst[i + 3 * gstride];
            int s0 = src[i],               s1 = src[i + gstride];
            int s2 = src[i + 2 * gstride], s3 = src[i + 3 * gstride];
            int p0 = atomicAdd(&g_rowptr[d0], 1);
            int p1 = atomicAdd(&g_rowptr[d1], 1);
            int p2 = atomicAdd(&g_rowptr[d2], 1);
            int p3 = atomicAdd(&g_rowptr[d3], 1);
            g_csr[p0] = s0; g_csr[p1] = s1; g_csr[p2] = s2; g_csr[p3] = s3;
        }
        for (; i < e; i += gstride) {
            int p = atomicAdd(&g_rowptr[dst[i]], 1);
            g_csr[p] = src[i];
        }
    }
}

// fp16 row-chunk accumulate: 8 halves (uint4) -> 4 float2
__device__ __forceinline__ void acc8(float2 a[4], uint4 v) {
    __half2* h = (__half2*)&v;
    #pragma unroll
    for (int m = 0; m < 4; m++) {
        float2 f = __half22float2(h[m]);
        a[m].x += f.x; a[m].y += f.y;
    }
}

// gather a node's in-edges into fp32 accumulators (8 lanes/node, lane=c)
__device__ __forceinline__ void gather_node(const uint4* __restrict__ hv,
                                            int rs, int d, int c, float2 a[4]) {
    int k = 0;
    for (; k + 8 <= d; k += 8) {
        int s[8];
        #pragma unroll
        for (int m = 0; m < 8; m++) s[m] = g_csr[rs + k + m];
        uint4 v[8];
        #pragma unroll
        for (int m = 0; m < 8; m++) v[m] = hv[(size_t)s[m] * 8 + c];
        #pragma unroll
        for (int m = 0; m < 8; m++) acc8(a, v[m]);
    }
    if (k + 4 <= d) {
        int s0 = g_csr[rs + k],     s1 = g_csr[rs + k + 1];
        int s2 = g_csr[rs + k + 2], s3 = g_csr[rs + k + 3];
        uint4 v0 = hv[(size_t)s0 * 8 + c];
        uint4 v1 = hv[(size_t)s1 * 8 + c];
        uint4 v2 = hv[(size_t)s2 * 8 + c];
        uint4 v3 = hv[(size_t)s3 * 8 + c];
        acc8(a, v0); acc8(a, v1); acc8(a, v2); acc8(a, v3);
        k += 4;
    }
    for (; k < d; k++) {
        uint4 v = hv[(size_t)g_csr[rs + k] * 8 + c];
        acc8(a, v);
    }
}

// layer-1 gather + relu -> h1 (fp16). NO smem: max occupancy for latency hiding.
__global__ void __launch_bounds__(256) k_gather1(const float* __restrict__ b1, int n) {
    int tid = threadIdx.x;
    int w = tid >> 5, lane = tid & 31;
    int grp = lane >> 3, c = lane & 7;
    int i = blockIdx.x * 32 + w * 4 + grp;
    if (i >= n) return;

    const uint4* hv = (const uint4*)g_hsH;
    int re = g_rowptr[i];                          // row end
    int d  = g_deg[i];
    int rs = re - d;
    float2 a[4];
    uint4 sv = hv[(size_t)i * 8 + c];              // self-loop
    {   __half2* h = (__half2*)&sv;
        #pragma unroll
        for (int m = 0; m < 4; m++) a[m] = __half22float2(h[m]); }
    gather_node(hv, rs, d, c, a);
    float dinv = g_dinv[i];
    union { uint4 u; __half2 h[4]; } pk;
    #pragma unroll
    for (int m = 0; m < 4; m++) {
        float2 bb = ((const float2*)b1)[4 * c + m];
        float r0 = fmaxf(fmaf(dinv, a[m].x, bb.x), 0.f);
        float r1 = fmaxf(fmaf(dinv, a[m].y, bb.y), 0.f);
        pk.h[m] = __floats2half2_rn(r0, r1);
    }
    ((uint4*)g_h1H)[(size_t)i * 8 + c] = pk.u;
}

// layer-2 GEMM (register-blocked, coalesced): hs2 = (h1 @ W2) * dinv, fp16 out
// Also zeroes g_gsum (runs before k_agg2 in stream order).
__global__ void k_gemm2(const float* __restrict__ W2, int n) {
    __shared__ float W2s[F][68];                   // [k][j], padded row
    __shared__ float h1s[128][65];
    __shared__ float dvs[128];
    int tid = threadIdx.x;
    if (blockIdx.x == 0 && tid < F) g_gsum[tid] = 0.f;
    for (int t = tid; t < F * F; t += 256) {
        int k = t >> 6, j = t & 63;
        W2s[k][j] = W2[t];
    }
    int base = blockIdx.x * 128;
    for (int t = tid; t < 128 * 8; t += 256) {
        int nl = t >> 3, c = t & 7;
        int i = base + nl;
        uint4 u = (i < n) ? ((const uint4*)g_h1H)[(size_t)i * 8 + c]
                          : make_uint4(0, 0, 0, 0);
        __half2* h = (__half2*)&u;
        #pragma unroll
        for (int m = 0; m < 4; m++) {
            float2 f = __half22float2(h[m]);
            h1s[nl][8 * c + 2 * m]     = f.x;
            h1s[nl][8 * c + 2 * m + 1] = f.y;
        }
        if (c == 0) dvs[nl] = (i < n) ? g_dinv[i] : 0.f;
    }
    __syncthreads();

    int c2 = tid & 7, q = tid >> 3;
    float acc[4][8];
    #pragma unroll
    for (int r = 0; r < 4; r++)
        #pragma unroll
        for (int m = 0; m < 8; m++) acc[r][m] = 0.f;
    #pragma unroll 8
    for (int k = 0; k < F; k++) {
        float4 wa = *(const float4*)&W2s[k][8 * c2];
        float4 wb = *(const float4*)&W2s[k][8 * c2 + 4];
        #pragma unroll
        for (int r = 0; r < 4; r++) {
            float h = h1s[q * 4 + r][k];
            acc[r][0] = fmaf(h, wa.x, acc[r][0]);
            acc[r][1] = fmaf(h, wa.y, acc[r][1]);
            acc[r][2] = fmaf(h, wa.z, acc[r][2]);
            acc[r][3] = fmaf(h, wa.w, acc[r][3]);
            acc[r][4] = fmaf(h, wb.x, acc[r][4]);
            acc[r][5] = fmaf(h, wb.y, acc[r][5]);
            acc[r][6] = fmaf(h, wb.z, acc[r][6]);
            acc[r][7] = fmaf(h, wb.w, acc[r][7]);
        }
    }
    #pragma unroll
    for (int r = 0; r < 4; r++) {
        int nl = q * 4 + r;
        int i = base + nl;
        if (i < n) {
            float dinv = dvs[nl];
            union { uint4 u; __half2 h[4]; } pk;
            #pragma unroll
            for (int m = 0; m < 4; m++)
                pk.h[m] = __floats2half2_rn(acc[r][2 * m] * dinv, acc[r][2 * m + 1] * dinv);
            ((uint4*)g_hs2H)[(size_t)i * 8 + c2] = pk.u;
        }
    }
}

// layer-2 gather + mean-pool partials (b2 folded at head); exact-cover grid
__global__ void __launch_bounds__(256) k_agg2(int n) {
    __shared__ float bsum[F];
    int tid = threadIdx.x, w = tid >> 5, lane = tid & 31;
    int grp = lane >> 3, c = lane & 7;
    if (tid < F) bsum[tid] = 0.f;
    __syncthreads();

    const uint4* hv = (const uint4*)g_hs2H;
    float2 asum[4] = {{0,0},{0,0},{0,0},{0,0}};
    int i = blockIdx.x * 32 + w * 4 + grp;
    if (i < n) {
        int re = g_rowptr[i];
        int d  = g_deg[i];
        int rs = re - d;
        float2 a[4];
        uint4 sv = hv[(size_t)i * 8 + c];
        {   __half2* h = (__half2*)&sv;
            #pragma unroll
            for (int m = 0; m < 4; m++) a[m] = __half22float2(h[m]); }
        gather_node(hv, rs, d, c, a);
        float dinv = g_dinv[i];
        #pragma unroll
        for (int m = 0; m < 4; m++) {
            asum[m].x = dinv * a[m].x;
            asum[m].y = dinv * a[m].y;
        }
    }
    #pragma unroll
    for (int m = 0; m < 4; m++) {
        asum[m].x += __shfl_xor_sync(0xffffffffu, asum[m].x, 8);
        asum[m].y += __shfl_xor_sync(0xffffffffu, asum[m].y, 8);
        asum[m].x += __shfl_xor_sync(0xffffffffu, asum[m].x, 16);
        asum[m].y += __shfl_xor_sync(0xffffffffu, asum[m].y, 16);
    }
    if (grp == 0) {
        #pragma unroll
        for (int m = 0; m < 4; m++) {
            atomicAdd(&bsum[8 * c + 2 * m],     asum[m].x);
            atomicAdd(&bsum[8 * c + 2 * m + 1], asum[m].y);
        }
    }
    __syncthreads();
    if (tid < F) atomicAdd(&g_gsum[tid], bsum[tid]);
}

// head: g = gsum/n + b2 ; s = relu(state@Wm + bm) ; out = [g,s] @ Wc + bc
__global__ void k_final(const float* __restrict__ state, const float* __restrict__ Wm,
                        const float* __restrict__ bm, const float* __restrict__ Wc,
                        const float* __restrict__ bc, const float* __restrict__ b2,
                        float* __restrict__ out, int n) {
    __shared__ float c128[128];
    int j = threadIdx.x;                           // 128 threads
    if (j < 64) {
        c128[j] = g_gsum[j] / (float)n + b2[j];
    } else {
        int jj = j - 64;
        float s = bm[jj];
        #pragma unroll
        for (int k = 0; k < 8; k++) s += state[k] * Wm[k * 64 + jj];
        c128[j] = fmaxf(s, 0.f);
    }
    __syncthreads();
    if (j < 2) {
        float s = bc[j];
        for (int k = 0; k < 128; k++) s += c128[k] * Wc[k * 2 + j];
        out[j] = s;
    }
}

// ---------------------------------------------------------------------------
extern "C" void kernel_launch(void* const* d_in, const int* in_sizes, int n_in,
                              void* d_out, int out_size) {
    const float* x     = (const float*)d_in[0];
    const float* state = (const float*)d_in[1];
    const float* W1    = (const float*)d_in[2];
    const float* b1    = (const float*)d_in[3];
    const float* W2    = (const float*)d_in[4];
    const float* b2    = (const float*)d_in[5];
    const float* Wm    = (const float*)d_in[6];
    const float* bm    = (const float*)d_in[7];
    const float* Wc    = (const float*)d_in[8];
    const float* bc    = (const float*)d_in[9];
    const int*   ei    = (const int*)d_in[10];
    float* out         = (float*)d_out;

    int n = in_sizes[0] / 8;       // 100000
    int e = in_sizes[10] / 2;      // 1250000
    const int* src = ei;
    const int* dst = ei + e;

    void* p_bar = nullptr;
    cudaGetSymbolAddress(&p_bar, g_barstate);
    cudaMemsetAsync(p_bar, 0, 2 * sizeof(int));

    const int T = 256;
    k_build<<<GRID_P1, T>>>(x, W1, src, dst, n, e);
    k_gather1<<<(n + 31) / 32, T>>>(b1, n);
    k_gemm2<<<(n + 127) / 128, T>>>(W2, n);
    k_agg2<<<(n + 31) / 32, T>>>(n);
    k_final<<<1, 128>>>(state, Wm, bm, Wc, bc, b2, out, n);
}

// round 15
// speedup vs baseline: 1.1460x; 1.1460x over previous
#include <cuda_runtime.h>
#include <cuda_fp16.h>

#define NMAX 100000
#define EMAX 1250000
#define F 64

// Scratch (__device__ globals; no allocation allowed)
__device__ int   g_deg[NMAX];
__device__ int   g_rowtmp[NMAX];
__device__ int   g_rowptr[NMAX];     // after k_fill: row END (start+deg)
__device__ float g_dinv[NMAX];
__device__ int   g_bsum[128];
__device__ int   g_csr[EMAX];
__device__ __align__(16) __half g_hsH [NMAX * F];  // layer-1 dinv-prescaled (fp16)
__device__ __align__(16) __half g_h1H [NMAX * F];  // relu(layer-1 out) (fp16)
__device__ __align__(16) __half g_hs2H[NMAX * F];  // layer-2 dinv-prescaled (fp16)
__device__ float g_gsum[F];

// ---------------------------------------------------------------------------
// in-degree count, 8 edges per thread for ATOMG MLP
__global__ void k_deg(const int* __restrict__ dst, int e) {
    int t = blockIdx.x * blockDim.x + threadIdx.x;
    int stride = gridDim.x * blockDim.x;
    int i = t;
    for (; i + 7 * stride < e; i += 8 * stride) {
        int d[8];
        #pragma unroll
        for (int m = 0; m < 8; m++) d[m] = dst[i + m * stride];
        #pragma unroll
        for (int m = 0; m < 8; m++) atomicAdd(&g_deg[d[m]], 1);
    }
    for (; i < e; i += stride) atomicAdd(&g_deg[dst[i]], 1);
}

// scan pass 1 (1024 threads, shfl) + dinv + FUSED layer-1 GEMM (fp16 out)
__global__ void k_scan1_gemm1(const float* __restrict__ x, const float* __restrict__ W1, int n) {
    __shared__ int wsum[32];
    __shared__ float W1t[F][12];                   // W1t[j][k], row 48B
    int tid = threadIdx.x, lane = tid & 31, wid = tid >> 5;
    if (tid < F * 8) {
        int k = tid >> 6, j = tid & 63;
        W1t[j][k] = W1[tid];
    }
    int i = blockIdx.x * 1024 + tid;
    int v = (i < n) ? g_deg[i] : 0;
    int xsc = v;
    #pragma unroll
    for (int off = 1; off < 32; off <<= 1) {
        int t = __shfl_up_sync(0xffffffffu, xsc, off);
        if (lane >= off) xsc += t;
    }
    if (lane == 31) wsum[wid] = xsc;
    __syncthreads();
    if (wid == 0) {
        int y = wsum[lane];
        #pragma unroll
        for (int off = 1; off < 32; off <<= 1) {
            int t = __shfl_up_sync(0xffffffffu, y, off);
            if (lane >= off) y += t;
        }
        wsum[lane] = y;
    }
    __syncthreads();
    if (i < n) {
        g_rowtmp[i] = xsc - v + (wid > 0 ? wsum[wid - 1] : 0);
        float dinv = rsqrtf((float)(v + 1));
        g_dinv[i] = dinv;
        float4 xa = ((const float4*)x)[i * 2];
        float4 xb = ((const float4*)x)[i * 2 + 1];
        #pragma unroll
        for (int c = 0; c < 8; c++) {
            union { uint4 u; __half2 h[4]; } pk;
            #pragma unroll
            for (int m = 0; m < 4; m++) {
                float s[2];
                #pragma unroll
                for (int t = 0; t < 2; t++) {
                    int j = 8 * c + 2 * m + t;
                    float4 wa = *(const float4*)&W1t[j][0];
                    float4 wb = *(const float4*)&W1t[j][4];
                    s[t] = (xa.x*wa.x + xa.y*wa.y + xa.z*wa.z + xa.w*wa.w
                          + xb.x*wb.x + xb.y*wb.y + xb.z*wb.z + xb.w*wb.w) * dinv;
                }
                pk.h[m] = __floats2half2_rn(s[0], s[1]);
            }
            ((uint4*)g_hsH)[(size_t)i * 8 + c] = pk.u;
        }
    }
    if (tid == 0) g_bsum[blockIdx.x] = wsum[31];
}

// scan pass 2+3 fused: each block scans <=128 block sums (shfl), then applies
__global__ void k_scan23(int n, int nb) {
    __shared__ int wsum[4];
    __shared__ int boffs[128];
    int tid = threadIdx.x, lane = tid & 31, wid = tid >> 5;
    int v = 0, xv = 0;
    if (tid < 128) {
        v = (tid < nb) ? g_bsum[tid] : 0;
        xv = v;
        #pragma unroll
        for (int off = 1; off < 32; off <<= 1) {
            int t = __shfl_up_sync(0xffffffffu, xv, off);
            if (lane >= off) xv += t;
        }
        if (lane == 31) wsum[wid] = xv;
    }
    __syncthreads();
    if (tid < 128) {
        int base = 0;
        for (int w = 0; w < wid; w++) base += wsum[w];
        boffs[tid] = base + xv - v;                // exclusive
    }
    __syncthreads();
    int i = blockIdx.x * blockDim.x + tid;
    if (i < n) g_rowptr[i] = g_rowtmp[i] + boffs[i >> 10];
}

// CSR fill (advances g_rowptr to row END), 4 edges per thread (measured best)
__global__ void k_fill(const int* __restrict__ src, const int* __restrict__ dst, int e) {
    int t = blockIdx.x * blockDim.x + threadIdx.x;
    int stride = gridDim.x * blockDim.x;
    int i = t;
    for (; i + 3 * stride < e; i += 4 * stride) {
        int d0 = dst[i],              d1 = dst[i + stride];
        int d2 = dst[i + 2 * stride], d3 = dst[i + 3 * stride];
        int s0 = src[i],              s1 = src[i + stride];
        int s2 = src[i + 2 * stride], s3 = src[i + 3 * stride];
        int p0 = atomicAdd(&g_rowptr[d0], 1);
        int p1 = atomicAdd(&g_rowptr[d1], 1);
        int p2 = atomicAdd(&g_rowptr[d2], 1);
        int p3 = atomicAdd(&g_rowptr[d3], 1);
        g_csr[p0] = s0; g_csr[p1] = s1; g_csr[p2] = s2; g_csr[p3] = s3;
    }
    for (; i < e; i += stride) {
        int p = atomicAdd(&g_rowptr[dst[i]], 1);
        g_csr[p] = src[i];
    }
}

// fp16-native accumulate: 4 HADD2 per 16B chunk (vs 16 cvt/add in fp32)
__device__ __forceinline__ void hacc(__half2 a[4], uint4 v) {
    __half2* h = (__half2*)&v;
    #pragma unroll
    for (int m = 0; m < 4; m++) a[m] = __hadd2(a[m], h[m]);
}

// gather a node's in-edges into fp16 accumulators (8 lanes/node, lane=c)
__device__ __forceinline__ void gather_node_h(const uint4* __restrict__ hv,
                                              int rs, int d, int c, __half2 a[4]) {
    int k = 0;
    for (; k + 8 <= d; k += 8) {
        int s[8];
        #pragma unroll
        for (int m = 0; m < 8; m++) s[m] = g_csr[rs + k + m];
        uint4 v[8];
        #pragma unroll
        for (int m = 0; m < 8; m++) v[m] = hv[(size_t)s[m] * 8 + c];
        #pragma unroll
        for (int m = 0; m < 8; m++) hacc(a, v[m]);
    }
    if (k + 4 <= d) {
        int s0 = g_csr[rs + k],     s1 = g_csr[rs + k + 1];
        int s2 = g_csr[rs + k + 2], s3 = g_csr[rs + k + 3];
        uint4 v0 = hv[(size_t)s0 * 8 + c];
        uint4 v1 = hv[(size_t)s1 * 8 + c];
        uint4 v2 = hv[(size_t)s2 * 8 + c];
        uint4 v3 = hv[(size_t)s3 * 8 + c];
        hacc(a, v0); hacc(a, v1); hacc(a, v2); hacc(a, v3);
        k += 4;
    }
    for (; k < d; k++) {
        uint4 v = hv[(size_t)g_csr[rs + k] * 8 + c];
        hacc(a, v);
    }
}

// layer-1 gather + relu -> h1 (fp16). NO smem: max occupancy for latency hiding.
__global__ void __launch_bounds__(256) k_gather1(const float* __restrict__ b1, int n) {
    int tid = threadIdx.x;
    int w = tid >> 5, lane = tid & 31;
    int grp = lane >> 3, c = lane & 7;
    int i = blockIdx.x * 32 + w * 4 + grp;
    if (i >= n) return;

    const uint4* hv = (const uint4*)g_hsH;
    int re = g_rowptr[i];                          // row end
    int d  = g_deg[i];
    int rs = re - d;
    __half2 a[4];
    uint4 sv = hv[(size_t)i * 8 + c];              // self-loop (init accumulators)
    {   __half2* h = (__half2*)&sv;
        #pragma unroll
        for (int m = 0; m < 4; m++) a[m] = h[m]; }
    gather_node_h(hv, rs, d, c, a);
    float dinv = g_dinv[i];
    union { uint4 u; __half2 h[4]; } pk;
    #pragma unroll
    for (int m = 0; m < 4; m++) {
        float2 f = __half22float2(a[m]);
        float2 bb = ((const float2*)b1)[4 * c + m];
        float r0 = fmaxf(fmaf(dinv, f.x, bb.x), 0.f);
        float r1 = fmaxf(fmaf(dinv, f.y, bb.y), 0.f);
        pk.h[m] = __floats2half2_rn(r0, r1);
    }
    ((uint4*)g_h1H)[(size_t)i * 8 + c] = pk.u;
}

// layer-2 GEMM (register-blocked, coalesced): hs2 = (h1 @ W2) * dinv, fp16 out
// Also zeroes g_gsum (runs before k_agg2 in stream order).
__global__ void k_gemm2(const float* __restrict__ W2, int n) {
    __shared__ float W2s[F][68];                   // [k][j], padded row
    __shared__ float h1s[128][65];
    __shared__ float dvs[128];
    int tid = threadIdx.x;
    if (blockIdx.x == 0 && tid < F) g_gsum[tid] = 0.f;
    for (int t = tid; t < F * F; t += 256) {
        int k = t >> 6, j = t & 63;
        W2s[k][j] = W2[t];
    }
    int base = blockIdx.x * 128;
    for (int t = tid; t < 128 * 8; t += 256) {
        int nl = t >> 3, c = t & 7;
        int i = base + nl;
        uint4 u = (i < n) ? ((const uint4*)g_h1H)[(size_t)i * 8 + c]
                          : make_uint4(0, 0, 0, 0);
        __half2* h = (__half2*)&u;
        #pragma unroll
        for (int m = 0; m < 4; m++) {
            float2 f = __half22float2(h[m]);
            h1s[nl][8 * c + 2 * m]     = f.x;
            h1s[nl][8 * c + 2 * m + 1] = f.y;
        }
        if (c == 0) dvs[nl] = (i < n) ? g_dinv[i] : 0.f;
    }
    __syncthreads();

    int c2 = tid & 7, q = tid >> 3;
    float acc[4][8];
    #pragma unroll
    for (int r = 0; r < 4; r++)
        #pragma unroll
        for (int m = 0; m < 8; m++) acc[r][m] = 0.f;
    #pragma unroll 8
    for (int k = 0; k < F; k++) {
        float4 wa = *(const float4*)&W2s[k][8 * c2];
        float4 wb = *(const float4*)&W2s[k][8 * c2 + 4];
        #pragma unroll
        for (int r = 0; r < 4; r++) {
            float h = h1s[q * 4 + r][k];
            acc[r][0] = fmaf(h, wa.x, acc[r][0]);
            acc[r][1] = fmaf(h, wa.y, acc[r][1]);
            acc[r][2] = fmaf(h, wa.z, acc[r][2]);
            acc[r][3] = fmaf(h, wa.w, acc[r][3]);
            acc[r][4] = fmaf(h, wb.x, acc[r][4]);
            acc[r][5] = fmaf(h, wb.y, acc[r][5]);
            acc[r][6] = fmaf(h, wb.z, acc[r][6]);
            acc[r][7] = fmaf(h, wb.w, acc[r][7]);
        }
    }
    #pragma unroll
    for (int r = 0; r < 4; r++) {
        int nl = q * 4 + r;
        int i = base + nl;
        if (i < n) {
            float dinv = dvs[nl];
            union { uint4 u; __half2 h[4]; } pk;
            #pragma unroll
            for (int m = 0; m < 4; m++)
                pk.h[m] = __floats2half2_rn(acc[r][2 * m] * dinv, acc[r][2 * m + 1] * dinv);
            ((uint4*)g_hs2H)[(size_t)i * 8 + c2] = pk.u;
        }
    }
}

// layer-2 gather + mean-pool partials (b2 folded at head); exact-cover grid
__global__ void __launch_bounds__(256) k_agg2(int n) {
    __shared__ float bsum[F];
    int tid = threadIdx.x, w = tid >> 5, lane = tid & 31;
    int grp = lane >> 3, c = lane & 7;
    if (tid < F) bsum[tid] = 0.f;
    __syncthreads();

    const uint4* hv = (const uint4*)g_hs2H;
    float2 asum[4] = {{0,0},{0,0},{0,0},{0,0}};
    int i = blockIdx.x * 32 + w * 4 + grp;
    if (i < n) {
        int re = g_rowptr[i];
        int d  = g_deg[i];
        int rs = re - d;
        __half2 a[4];
        uint4 sv = hv[(size_t)i * 8 + c];
        {   __half2* h = (__half2*)&sv;
            #pragma unroll
            for (int m = 0; m < 4; m++) a[m] = h[m]; }
        gather_node_h(hv, rs, d, c, a);
        float dinv = g_dinv[i];
        #pragma unroll
        for (int m = 0; m < 4; m++) {
            float2 f = __half22float2(a[m]);
            asum[m].x = dinv * f.x;
            asum[m].y = dinv * f.y;
        }
    }
    #pragma unroll
    for (int m = 0; m < 4; m++) {
        asum[m].x += __shfl_xor_sync(0xffffffffu, asum[m].x, 8);
        asum[m].y += __shfl_xor_sync(0xffffffffu, asum[m].y, 8);
        asum[m].x += __shfl_xor_sync(0xffffffffu, asum[m].x, 16);
        asum[m].y += __shfl_xor_sync(0xffffffffu, asum[m].y, 16);
    }
    if (grp == 0) {
        #pragma unroll
        for (int m = 0; m < 4; m++) {
            atomicAdd(&bsum[8 * c + 2 * m],     asum[m].x);
            atomicAdd(&bsum[8 * c + 2 * m + 1], asum[m].y);
        }
    }
    __syncthreads();
    if (tid < F) atomicAdd(&g_gsum[tid], bsum[tid]);
}

// head: g = gsum/n + b2 ; s = relu(state@Wm + bm) ; out = [g,s] @ Wc + bc
__global__ void k_final(const float* __restrict__ state, const float* __restrict__ Wm,
                        const float* __restrict__ bm, const float* __restrict__ Wc,
                        const float* __restrict__ bc, const float* __restrict__ b2,
                        float* __restrict__ out, int n) {
    __shared__ float c128[128];
    int j = threadIdx.x;                           // 128 threads
    if (j < 64) {
        c128[j] = g_gsum[j] / (float)n + b2[j];
    } else {
        int jj = j - 64;
        float s = bm[jj];
        #pragma unroll
        for (int k = 0; k < 8; k++) s += state[k] * Wm[k * 64 + jj];
        c128[j] = fmaxf(s, 0.f);
    }
    __syncthreads();
    if (j < 2) {
        float s = bc[j];
        for (int k = 0; k < 128; k++) s += c128[k] * Wc[k * 2 + j];
        out[j] = s;
    }
}

// ---------------------------------------------------------------------------
extern "C" void kernel_launch(void* const* d_in, const int* in_sizes, int n_in,
                              void* d_out, int out_size) {
    const float* x     = (const float*)d_in[0];
    const float* state = (const float*)d_in[1];
    const float* W1    = (const float*)d_in[2];
    const float* b1    = (const float*)d_in[3];
    const float* W2    = (const float*)d_in[4];
    const float* b2    = (const float*)d_in[5];
    const float* Wm    = (const float*)d_in[6];
    const float* bm    = (const float*)d_in[7];
    const float* Wc    = (const float*)d_in[8];
    const float* bc    = (const float*)d_in[9];
    const int*   ei    = (const int*)d_in[10];
    float* out         = (float*)d_out;

    int n = in_sizes[0] / 8;       // 100000
    int e = in_sizes[10] / 2;      // 1250000
    const int* src = ei;
    const int* dst = ei + e;

    int nb1 = (n + 1023) / 1024;   // 98 <= 128

    void* p_deg = nullptr;
    cudaGetSymbolAddress(&p_deg, g_deg);
    cudaMemsetAsync(p_deg, 0, (size_t)n * sizeof(int));

    const int T = 256;
    k_deg<<<1184, T>>>(dst, e);
    k_scan1_gemm1<<<nb1, 1024>>>(x, W1, n);
    k_scan23<<<(n + T - 1) / T, T>>>(n, nb1);
    k_fill<<<1184, T>>>(src, dst, e);
    k_gather1<<<(n + 31) / 32, T>>>(b1, n);
    k_gemm2<<<(n + 127) / 128, T>>>(W2, n);
    k_agg2<<<(n + 31) / 32, T>>>(n);
    k_final<<<1, 128>>>(state, Wm, bm, Wc, bc, b2, out, n);
}

// round 16
// speedup vs baseline: 1.3039x; 1.1378x over previous
#include <cuda_runtime.h>
#include <cuda_fp16.h>

#define NMAX 100000
#define EMAX 1250000
#define F 64

// Scratch (__device__ globals; no allocation allowed)
__device__ int   g_deg[NMAX];
__device__ int   g_rowtmp[NMAX];
__device__ int   g_rowptr[NMAX];     // after k_fill: row END (start+deg)
__device__ float g_dinv[NMAX];
__device__ int   g_bsum[128];
__device__ int   g_csr[EMAX];
__device__ __align__(16) __half g_hsH [NMAX * F];  // layer-1 dinv-prescaled (fp16)
__device__ __align__(16) __half g_h1H [NMAX * F];  // relu(layer-1 out) (fp16)
__device__ __align__(16) __half g_hs2H[NMAX * F];  // layer-2 dinv-prescaled (fp16)
__device__ float g_gsum[F];

// ---------------------------------------------------------------------------
// in-degree count: int4 edge loads, 8 atomics in flight
__global__ void k_deg(const int* __restrict__ dst, int e) {
    int t = blockIdx.x * blockDim.x + threadIdx.x;
    int stride = gridDim.x * blockDim.x;
    int e4 = e >> 2;
    const int4* dst4 = (const int4*)dst;
    int i = t;
    for (; i + stride < e4; i += 2 * stride) {
        int4 a = dst4[i];
        int4 b = dst4[i + stride];
        atomicAdd(&g_deg[a.x], 1); atomicAdd(&g_deg[a.y], 1);
        atomicAdd(&g_deg[a.z], 1); atomicAdd(&g_deg[a.w], 1);
        atomicAdd(&g_deg[b.x], 1); atomicAdd(&g_deg[b.y], 1);
        atomicAdd(&g_deg[b.z], 1); atomicAdd(&g_deg[b.w], 1);
    }
    for (; i < e4; i += stride) {
        int4 a = dst4[i];
        atomicAdd(&g_deg[a.x], 1); atomicAdd(&g_deg[a.y], 1);
        atomicAdd(&g_deg[a.z], 1); atomicAdd(&g_deg[a.w], 1);
    }
    for (int k = (e4 << 2) + t; k < e; k += stride) atomicAdd(&g_deg[dst[k]], 1);
}

// scan pass 1 (1024 threads, shfl) + dinv + FUSED layer-1 GEMM (fp16 out)
__global__ void k_scan1_gemm1(const float* __restrict__ x, const float* __restrict__ W1, int n) {
    __shared__ int wsum[32];
    __shared__ float W1t[F][12];                   // W1t[j][k], row 48B
    int tid = threadIdx.x, lane = tid & 31, wid = tid >> 5;
    if (tid < F * 8) {
        int k = tid >> 6, j = tid & 63;
        W1t[j][k] = W1[tid];
    }
    int i = blockIdx.x * 1024 + tid;
    int v = (i < n) ? g_deg[i] : 0;
    int xsc = v;
    #pragma unroll
    for (int off = 1; off < 32; off <<= 1) {
        int t = __shfl_up_sync(0xffffffffu, xsc, off);
        if (lane >= off) xsc += t;
    }
    if (lane == 31) wsum[wid] = xsc;
    __syncthreads();
    if (wid == 0) {
        int y = wsum[lane];
        #pragma unroll
        for (int off = 1; off < 32; off <<= 1) {
            int t = __shfl_up_sync(0xffffffffu, y, off);
            if (lane >= off) y += t;
        }
        wsum[lane] = y;
    }
    __syncthreads();
    if (i < n) {
        g_rowtmp[i] = xsc - v + (wid > 0 ? wsum[wid - 1] : 0);
        float dinv = rsqrtf((float)(v + 1));
        g_dinv[i] = dinv;
        float4 xa = ((const float4*)x)[i * 2];
        float4 xb = ((const float4*)x)[i * 2 + 1];
        #pragma unroll
        for (int c = 0; c < 8; c++) {
            union { uint4 u; __half2 h[4]; } pk;
            #pragma unroll
            for (int m = 0; m < 4; m++) {
                float s[2];
                #pragma unroll
                for (int t = 0; t < 2; t++) {
                    int j = 8 * c + 2 * m + t;
                    float4 wa = *(const float4*)&W1t[j][0];
                    float4 wb = *(const float4*)&W1t[j][4];
                    s[t] = (xa.x*wa.x + xa.y*wa.y + xa.z*wa.z + xa.w*wa.w
                          + xb.x*wb.x + xb.y*wb.y + xb.z*wb.z + xb.w*wb.w) * dinv;
                }
                pk.h[m] = __floats2half2_rn(s[0], s[1]);
            }
            ((uint4*)g_hsH)[(size_t)i * 8 + c] = pk.u;
        }
    }
    if (tid == 0) g_bsum[blockIdx.x] = wsum[31];
}

// scan pass 2+3 fused: each block scans <=128 block sums (shfl), then applies
__global__ void k_scan23(int n, int nb) {
    __shared__ int wsum[4];
    __shared__ int boffs[128];
    int tid = threadIdx.x, lane = tid & 31, wid = tid >> 5;
    int v = 0, xv = 0;
    if (tid < 128) {
        v = (tid < nb) ? g_bsum[tid] : 0;
        xv = v;
        #pragma unroll
        for (int off = 1; off < 32; off <<= 1) {
            int t = __shfl_up_sync(0xffffffffu, xv, off);
            if (lane >= off) xv += t;
        }
        if (lane == 31) wsum[wid] = xv;
    }
    __syncthreads();
    if (tid < 128) {
        int base = 0;
        for (int w = 0; w < wid; w++) base += wsum[w];
        boffs[tid] = base + xv - v;                // exclusive
    }
    __syncthreads();
    int i = blockIdx.x * blockDim.x + tid;
    if (i < n) g_rowptr[i] = g_rowtmp[i] + boffs[i >> 10];
}

// CSR fill: int4 edge loads, 4 atomics + 4 scattered stores per iteration
__global__ void k_fill(const int* __restrict__ src, const int* __restrict__ dst, int e) {
    int t = blockIdx.x * blockDim.x + threadIdx.x;
    int stride = gridDim.x * blockDim.x;
    int e4 = e >> 2;
    const int4* dst4 = (const int4*)dst;
    const int4* src4 = (const int4*)src;
    for (int i = t; i < e4; i += stride) {
        int4 d = dst4[i];
        int4 s = src4[i];
        int p0 = atomicAdd(&g_rowptr[d.x], 1);
        int p1 = atomicAdd(&g_rowptr[d.y], 1);
        int p2 = atomicAdd(&g_rowptr[d.z], 1);
        int p3 = atomicAdd(&g_rowptr[d.w], 1);
        g_csr[p0] = s.x; g_csr[p1] = s.y; g_csr[p2] = s.z; g_csr[p3] = s.w;
    }
    for (int k = (e4 << 2) + t; k < e; k += stride) {
        int p = atomicAdd(&g_rowptr[dst[k]], 1);
        g_csr[p] = src[k];
    }
}

// fp16-native accumulate: 4 HADD2 per 16B chunk
__device__ __forceinline__ void hacc(__half2 a[4], uint4 v) {
    __half2* h = (__half2*)&v;
    #pragma unroll
    for (int m = 0; m < 4; m++) a[m] = __hadd2(a[m], h[m]);
}

// gather a node's in-edges into fp16 accumulators (8 lanes/node, lane=c)
__device__ __forceinline__ void gather_node_h(const uint4* __restrict__ hv,
                                              int rs, int d, int c, __half2 a[4]) {
    int k = 0;
    for (; k + 8 <= d; k += 8) {
        int s[8];
        #pragma unroll
        for (int m = 0; m < 8; m++) s[m] = g_csr[rs + k + m];
        uint4 v[8];
        #pragma unroll
        for (int m = 0; m < 8; m++) v[m] = hv[(size_t)s[m] * 8 + c];
        #pragma unroll
        for (int m = 0; m < 8; m++) hacc(a, v[m]);
    }
    if (k + 4 <= d) {
        int s0 = g_csr[rs + k],     s1 = g_csr[rs + k + 1];
        int s2 = g_csr[rs + k + 2], s3 = g_csr[rs + k + 3];
        uint4 v0 = hv[(size_t)s0 * 8 + c];
        uint4 v1 = hv[(size_t)s1 * 8 + c];
        uint4 v2 = hv[(size_t)s2 * 8 + c];
        uint4 v3 = hv[(size_t)s3 * 8 + c];
        hacc(a, v0); hacc(a, v1); hacc(a, v2); hacc(a, v3);
        k += 4;
    }
    for (; k < d; k++) {
        uint4 v = hv[(size_t)g_csr[rs + k] * 8 + c];
        hacc(a, v);
    }
}

// layer-1 gather + relu -> h1 (fp16). NO smem: max occupancy for latency hiding.
__global__ void __launch_bounds__(256) k_gather1(const float* __restrict__ b1, int n) {
    int tid = threadIdx.x;
    int w = tid >> 5, lane = tid & 31;
    int grp = lane >> 3, c = lane & 7;
    int i = blockIdx.x * 32 + w * 4 + grp;
    if (i >= n) return;

    const uint4* hv = (const uint4*)g_hsH;
    int re = g_rowptr[i];                          // row end
    int d  = g_deg[i];
    int rs = re - d;
    __half2 a[4];
    uint4 sv = hv[(size_t)i * 8 + c];              // self-loop (init accumulators)
    {   __half2* h = (__half2*)&sv;
        #pragma unroll
        for (int m = 0; m < 4; m++) a[m] = h[m]; }
    gather_node_h(hv, rs, d, c, a);
    float dinv = g_dinv[i];
    union { uint4 u; __half2 h[4]; } pk;
    #pragma unroll
    for (int m = 0; m < 4; m++) {
        float2 f = __half22float2(a[m]);
        float2 bb = ((const float2*)b1)[4 * c + m];
        float r0 = fmaxf(fmaf(dinv, f.x, bb.x), 0.f);
        float r1 = fmaxf(fmaf(dinv, f.y, bb.y), 0.f);
        pk.h[m] = __floats2half2_rn(r0, r1);
    }
    ((uint4*)g_h1H)[(size_t)i * 8 + c] = pk.u;
}

// layer-2 GEMM, HFMA2 over k-pairs: hs2 = (h1 @ W2) * dinv, fp16 out.
// W2h[k2][j] = (W2[2k2][j], W2[2k2+1][j]); acc lo/hi hold even/odd-k partials.
// Also zeroes g_gsum (runs before k_agg2 in stream order).
__global__ void k_gemm2(const float* __restrict__ W2, int n) {
    __shared__ __half2 W2h[32][68];                // [k2][j], padded row
    __shared__ __half2 h1h[128][33];               // [node][k2], padded row
    __shared__ float dvs[128];
    int tid = threadIdx.x;
    if (blockIdx.x == 0 && tid < F) g_gsum[tid] = 0.f;
    for (int t = tid; t < 32 * F; t += 256) {
        int k2 = t >> 6, j = t & 63;
        W2h[k2][j] = __floats2half2_rn(W2[(2 * k2) * F + j], W2[(2 * k2 + 1) * F + j]);
    }
    int base = blockIdx.x * 128;
    for (int t = tid; t < 128 * 8; t += 256) {
        int nl = t >> 3, c = t & 7;
        int i = base + nl;
        uint4 u = (i < n) ? ((const uint4*)g_h1H)[(size_t)i * 8 + c]
                          : make_uint4(0, 0, 0, 0);
        __half2* hu = (__half2*)&u;
        h1h[nl][4 * c + 0] = hu[0];
        h1h[nl][4 * c + 1] = hu[1];
        h1h[nl][4 * c + 2] = hu[2];
        h1h[nl][4 * c + 3] = hu[3];
        if (c == 0) dvs[nl] = (i < n) ? g_dinv[i] : 0.f;
    }
    __syncthreads();

    int c2 = tid & 7, q = tid >> 3;
    __half2 acc[4][8];
    #pragma unroll
    for (int r = 0; r < 4; r++)
        #pragma unroll
        for (int m = 0; m < 8; m++) acc[r][m] = __floats2half2_rn(0.f, 0.f);
    #pragma unroll 4
    for (int k2 = 0; k2 < 32; k2++) {
        __half2 wv[8];
        *(uint4*)&wv[0] = *(const uint4*)&W2h[k2][8 * c2];
        *(uint4*)&wv[4] = *(const uint4*)&W2h[k2][8 * c2 + 4];
        #pragma unroll
        for (int r = 0; r < 4; r++) {
            __half2 h = h1h[q * 4 + r][k2];
            #pragma unroll
            for (int m = 0; m < 8; m++)
                acc[r][m] = __hfma2(h, wv[m], acc[r][m]);
        }
    }
    #pragma unroll
    for (int r = 0; r < 4; r++) {
        int nl = q * 4 + r;
        int i = base + nl;
        if (i < n) {
            float dinv = dvs[nl];
            union { uint4 u; __half2 h[4]; } pk;
            #pragma unroll
            for (int m2 = 0; m2 < 4; m2++) {
                float2 f0 = __half22float2(acc[r][2 * m2]);
                float2 f1 = __half22float2(acc[r][2 * m2 + 1]);
                pk.h[m2] = __floats2half2_rn((f0.x + f0.y) * dinv, (f1.x + f1.y) * dinv);
            }
            ((uint4*)g_hs2H)[(size_t)i * 8 + c2] = pk.u;
        }
    }
}

// layer-2 gather + mean-pool partials (b2 folded at head); exact-cover grid
__global__ void __launch_bounds__(256) k_agg2(int n) {
    __shared__ float bsum[F];
    int tid = threadIdx.x, w = tid >> 5, lane = tid & 31;
    int grp = lane >> 3, c = lane & 7;
    if (tid < F) bsum[tid] = 0.f;
    __syncthreads();

    const uint4* hv = (const uint4*)g_hs2H;
    float2 asum[4] = {{0,0},{0,0},{0,0},{0,0}};
    int i = blockIdx.x * 32 + w * 4 + grp;
    if (i < n) {
        int re = g_rowptr[i];
        int d  = g_deg[i];
        int rs = re - d;
        __half2 a[4];
        uint4 sv = hv[(size_t)i * 8 + c];
        {   __half2* h = (__half2*)&sv;
            #pragma unroll
            for (int m = 0; m < 4; m++) a[m] = h[m]; }
        gather_node_h(hv, rs, d, c, a);
        float dinv = g_dinv[i];
        #pragma unroll
        for (int m = 0; m < 4; m++) {
            float2 f = __half22float2(a[m]);
            asum[m].x = dinv * f.x;
            asum[m].y = dinv * f.y;
        }
    }
    #pragma unroll
    for (int m = 0; m < 4; m++) {
        asum[m].x += __shfl_xor_sync(0xffffffffu, asum[m].x, 8);
        asum[m].y += __shfl_xor_sync(0xffffffffu, asum[m].y, 8);
        asum[m].x += __shfl_xor_sync(0xffffffffu, asum[m].x, 16);
        asum[m].y += __shfl_xor_sync(0xffffffffu, asum[m].y, 16);
    }
    if (grp == 0) {
        #pragma unroll
        for (int m = 0; m < 4; m++) {
            atomicAdd(&bsum[8 * c + 2 * m],     asum[m].x);
            atomicAdd(&bsum[8 * c + 2 * m + 1], asum[m].y);
        }
    }
    __syncthreads();
    if (tid < F) atomicAdd(&g_gsum[tid], bsum[tid]);
}

// head: g = gsum/n + b2 ; s = relu(state@Wm + bm) ; out = [g,s] @ Wc + bc
__global__ void k_final(const float* __restrict__ state, const float* __restrict__ Wm,
                        const float* __restrict__ bm, const float* __restrict__ Wc,
                        const float* __restrict__ bc, const float* __restrict__ b2,
                        float* __restrict__ out, int n) {
    __shared__ float c128[128];
    int j = threadIdx.x;                           // 128 threads
    if (j < 64) {
        c128[j] = g_gsum[j] / (float)n + b2[j];
    } else {
        int jj = j - 64;
        float s = bm[jj];
        #pragma unroll
        for (int k = 0; k < 8; k++) s += state[k] * Wm[k * 64 + jj];
        c128[j] = fmaxf(s, 0.f);
    }
    __syncthreads();
    if (j < 2) {
        float s = bc[j];
        for (int k = 0; k < 128; k++) s += c128[k] * Wc[k * 2 + j];
        out[j] = s;
    }
}

// ---------------------------------------------------------------------------
extern "C" void kernel_launch(void* const* d_in, const int* in_sizes, int n_in,
                              void* d_out, int out_size) {
    const float* x     = (const float*)d_in[0];
    const float* state = (const float*)d_in[1];
    const float* W1    = (const float*)d_in[2];
    const float* b1    = (const float*)d_in[3];
    const float* W2    = (const float*)d_in[4];
    const float* b2    = (const float*)d_in[5];
    const float* Wm    = (const float*)d_in[6];
    const float* bm    = (const float*)d_in[7];
    const float* Wc    = (const float*)d_in[8];
    const float* bc    = (const float*)d_in[9];
    const int*   ei    = (const int*)d_in[10];
    float* out         = (float*)d_out;

    int n = in_sizes[0] / 8;       // 100000
    int e = in_sizes[10] / 2;      // 1250000
    const int* src = ei;
    const int* dst = ei + e;

    int nb1 = (n + 1023) / 1024;   // 98 <= 128

    void* p_deg = nullptr;
    cudaGetSymbolAddress(&p_deg, g_deg);
    cudaMemsetAsync(p_deg, 0, (size_t)n * sizeof(int));

    const int T = 256;
    k_deg<<<1184, T>>>(dst, e);
    k_scan1_gemm1<<<nb1, 1024>>>(x, W1, n);
    k_scan23<<<(n + T - 1) / T, T>>>(n, nb1);
    k_fill<<<1184, T>>>(src, dst, e);
    k_gather1<<<(n + 31) / 32, T>>>(b1, n);
    k_gemm2<<<(n + 127) / 128, T>>>(W2, n);
    k_agg2<<<(n + 31) / 32, T>>>(n);
    k_final<<<1, 128>>>(state, Wm, bm, Wc, bc, b2, out, n);
}

// round 17
// speedup vs baseline: 1.3242x; 1.0156x over previous
#include <cuda_runtime.h>
#include <cuda_fp16.h>

#define NMAX 100000
#define EMAX 1250000
#define F 64

// Scratch (__device__ globals; no allocation allowed)
__device__ int   g_deg[NMAX];
__device__ int   g_rowtmp[NMAX];     // block-local exclusive prefix of deg
__device__ int   g_boff[128];        // per-1024-chunk offsets
__device__ float g_dinv[NMAX];
__device__ int   g_bsum[128];
__device__ int   g_rank[EMAX];       // slot-within-row per edge (from deg atomics)
__device__ int   g_csr[EMAX];
__device__ __align__(16) __half g_hsH [NMAX * F];  // layer-1 dinv-prescaled (fp16)
__device__ __align__(16) __half g_h1H [NMAX * F];  // relu(layer-1 out) (fp16)
__device__ __align__(16) __half g_hs2H[NMAX * F];  // layer-2 dinv-prescaled (fp16)
__device__ float g_gsum[F];

// ---------------------------------------------------------------------------
// in-degree count + rank capture: rank[i] = this edge's slot within its row
__global__ void k_deg(const int* __restrict__ dst, int e) {
    int t = blockIdx.x * blockDim.x + threadIdx.x;
    int stride = gridDim.x * blockDim.x;
    int e4 = e >> 2;
    const int4* dst4 = (const int4*)dst;
    int4* rank4 = (int4*)g_rank;
    for (int i = t; i < e4; i += stride) {
        int4 a = dst4[i];
        int4 r;
        r.x = atomicAdd(&g_deg[a.x], 1);
        r.y = atomicAdd(&g_deg[a.y], 1);
        r.z = atomicAdd(&g_deg[a.z], 1);
        r.w = atomicAdd(&g_deg[a.w], 1);
        rank4[i] = r;
    }
    for (int k = (e4 << 2) + t; k < e; k += stride)
        g_rank[k] = atomicAdd(&g_deg[dst[k]], 1);
}

// scan pass 1 (1024 threads, shfl) + dinv + FUSED layer-1 GEMM (fp16 out)
__global__ void k_scan1_gemm1(const float* __restrict__ x, const float* __restrict__ W1, int n) {
    __shared__ int wsum[32];
    __shared__ float W1t[F][12];                   // W1t[j][k], row 48B
    int tid = threadIdx.x, lane = tid & 31, wid = tid >> 5;
    if (tid < F * 8) {
        int k = tid >> 6, j = tid & 63;
        W1t[j][k] = W1[tid];
    }
    int i = blockIdx.x * 1024 + tid;
    int v = (i < n) ? g_deg[i] : 0;
    int xsc = v;
    #pragma unroll
    for (int off = 1; off < 32; off <<= 1) {
        int t = __shfl_up_sync(0xffffffffu, xsc, off);
        if (lane >= off) xsc += t;
    }
    if (lane == 31) wsum[wid] = xsc;
    __syncthreads();
    if (wid == 0) {
        int y = wsum[lane];
        #pragma unroll
        for (int off = 1; off < 32; off <<= 1) {
            int t = __shfl_up_sync(0xffffffffu, y, off);
            if (lane >= off) y += t;
        }
        wsum[lane] = y;
    }
    __syncthreads();
    if (i < n) {
        g_rowtmp[i] = xsc - v + (wid > 0 ? wsum[wid - 1] : 0);
        float dinv = rsqrtf((float)(v + 1));
        g_dinv[i] = dinv;
        float4 xa = ((const float4*)x)[i * 2];
        float4 xb = ((const float4*)x)[i * 2 + 1];
        #pragma unroll
        for (int c = 0; c < 8; c++) {
            union { uint4 u; __half2 h[4]; } pk;
            #pragma unroll
            for (int m = 0; m < 4; m++) {
                float s[2];
                #pragma unroll
                for (int t = 0; t < 2; t++) {
                    int j = 8 * c + 2 * m + t;
                    float4 wa = *(const float4*)&W1t[j][0];
                    float4 wb = *(const float4*)&W1t[j][4];
                    s[t] = (xa.x*wa.x + xa.y*wa.y + xa.z*wa.z + xa.w*wa.w
                          + xb.x*wb.x + xb.y*wb.y + xb.z*wb.z + xb.w*wb.w) * dinv;
                }
                pk.h[m] = __floats2half2_rn(s[0], s[1]);
            }
            ((uint4*)g_hsH)[(size_t)i * 8 + c] = pk.u;
        }
    }
    if (tid == 0) g_bsum[blockIdx.x] = wsum[31];
}

// scan pass 2: one 128-thread block scans <=128 block sums -> g_boff
__global__ void k_scan2(int nb) {
    __shared__ int wsum[4];
    int tid = threadIdx.x, lane = tid & 31, wid = tid >> 5;
    int v = (tid < nb) ? g_bsum[tid] : 0;
    int xv = v;
    #pragma unroll
    for (int off = 1; off < 32; off <<= 1) {
        int t = __shfl_up_sync(0xffffffffu, xv, off);
        if (lane >= off) xv += t;
    }
    if (lane == 31) wsum[wid] = xv;
    __syncthreads();
    int base = 0;
    for (int w = 0; w < wid; w++) base += wsum[w];
    g_boff[tid] = base + xv - v;                   // exclusive
}

// CSR fill, atomic-free: slot = rowtmp[dst] + boff[dst>>10] + rank
__global__ void k_fill(const int* __restrict__ src, const int* __restrict__ dst, int e, int nb) {
    __shared__ int boffs[128];
    int tid = threadIdx.x;
    if (tid < 128) boffs[tid] = (tid < nb) ? g_boff[tid] : 0;
    __syncthreads();
    int t = blockIdx.x * blockDim.x + tid;
    int stride = gridDim.x * blockDim.x;
    int e4 = e >> 2;
    const int4* dst4 = (const int4*)dst;
    const int4* src4 = (const int4*)src;
    const int4* rank4 = (const int4*)g_rank;
    for (int i = t; i < e4; i += stride) {
        int4 d = dst4[i];
        int4 s = src4[i];
        int4 r = rank4[i];
        int p0 = g_rowtmp[d.x] + boffs[d.x >> 10] + r.x;
        int p1 = g_rowtmp[d.y] + boffs[d.y >> 10] + r.y;
        int p2 = g_rowtmp[d.z] + boffs[d.z >> 10] + r.z;
        int p3 = g_rowtmp[d.w] + boffs[d.w >> 10] + r.w;
        g_csr[p0] = s.x; g_csr[p1] = s.y; g_csr[p2] = s.z; g_csr[p3] = s.w;
    }
    for (int k = (e4 << 2) + t; k < e; k += stride) {
        int d = dst[k];
        g_csr[g_rowtmp[d] + boffs[d >> 10] + g_rank[k]] = src[k];
    }
}

// fp16-native accumulate: 4 HADD2 per 16B chunk
__device__ __forceinline__ void hacc(__half2 a[4], uint4 v) {
    __half2* h = (__half2*)&v;
    #pragma unroll
    for (int m = 0; m < 4; m++) a[m] = __hadd2(a[m], h[m]);
}

// gather a node's in-edges into fp16 accumulators (8 lanes/node, lane=c)
__device__ __forceinline__ void gather_node_h(const uint4* __restrict__ hv,
                                              int rs, int d, int c, __half2 a[4]) {
    int k = 0;
    for (; k + 8 <= d; k += 8) {
        int s[8];
        #pragma unroll
        for (int m = 0; m < 8; m++) s[m] = g_csr[rs + k + m];
        uint4 v[8];
        #pragma unroll
        for (int m = 0; m < 8; m++) v[m] = hv[(size_t)s[m] * 8 + c];
        #pragma unroll
        for (int m = 0; m < 8; m++) hacc(a, v[m]);
    }
    if (k + 4 <= d) {
        int s0 = g_csr[rs + k],     s1 = g_csr[rs + k + 1];
        int s2 = g_csr[rs + k + 2], s3 = g_csr[rs + k + 3];
        uint4 v0 = hv[(size_t)s0 * 8 + c];
        uint4 v1 = hv[(size_t)s1 * 8 + c];
        uint4 v2 = hv[(size_t)s2 * 8 + c];
        uint4 v3 = hv[(size_t)s3 * 8 + c];
        hacc(a, v0); hacc(a, v1); hacc(a, v2); hacc(a, v3);
        k += 4;
    }
    for (; k < d; k++) {
        uint4 v = hv[(size_t)g_csr[rs + k] * 8 + c];
        hacc(a, v);
    }
}

// layer-1 gather + relu -> h1 (fp16). NO smem: max occupancy for latency hiding.
__global__ void __launch_bounds__(256) k_gather1(const float* __restrict__ b1, int n) {
    int tid = threadIdx.x;
    int w = tid >> 5, lane = tid & 31;
    int grp = lane >> 3, c = lane & 7;
    int i = blockIdx.x * 32 + w * 4 + grp;
    if (i >= n) return;

    const uint4* hv = (const uint4*)g_hsH;
    int rs = g_rowtmp[i] + g_boff[i >> 10];        // row start
    int d  = g_deg[i];
    __half2 a[4];
    uint4 sv = hv[(size_t)i * 8 + c];              // self-loop (init accumulators)
    {   __half2* h = (__half2*)&sv;
        #pragma unroll
        for (int m = 0; m < 4; m++) a[m] = h[m]; }
    gather_node_h(hv, rs, d, c, a);
    float dinv = g_dinv[i];
    union { uint4 u; __half2 h[4]; } pk;
    #pragma unroll
    for (int m = 0; m < 4; m++) {
        float2 f = __half22float2(a[m]);
        float2 bb = ((const float2*)b1)[4 * c + m];
        float r0 = fmaxf(fmaf(dinv, f.x, bb.x), 0.f);
        float r1 = fmaxf(fmaf(dinv, f.y, bb.y), 0.f);
        pk.h[m] = __floats2half2_rn(r0, r1);
    }
    ((uint4*)g_h1H)[(size_t)i * 8 + c] = pk.u;
}

// layer-2 GEMM, HFMA2 over k-pairs: hs2 = (h1 @ W2) * dinv, fp16 out.
// Also zeroes g_gsum (runs before k_agg2 in stream order).
__global__ void k_gemm2(const float* __restrict__ W2, int n) {
    __shared__ __half2 W2h[32][68];                // [k2][j], padded row
    __shared__ __half2 h1h[128][33];               // [node][k2], padded row
    __shared__ float dvs[128];
    int tid = threadIdx.x;
    if (blockIdx.x == 0 && tid < F) g_gsum[tid] = 0.f;
    for (int t = tid; t < 32 * F; t += 256) {
        int k2 = t >> 6, j = t & 63;
        W2h[k2][j] = __floats2half2_rn(W2[(2 * k2) * F + j], W2[(2 * k2 + 1) * F + j]);
    }
    int base = blockIdx.x * 128;
    for (int t = tid; t < 128 * 8; t += 256) {
        int nl = t >> 3, c = t & 7;
        int i = base + nl;
        uint4 u = (i < n) ? ((const uint4*)g_h1H)[(size_t)i * 8 + c]
                          : make_uint4(0, 0, 0, 0);
        __half2* hu = (__half2*)&u;
        h1h[nl][4 * c + 0] = hu[0];
        h1h[nl][4 * c + 1] = hu[1];
        h1h[nl][4 * c + 2] = hu[2];
        h1h[nl][4 * c + 3] = hu[3];
        if (c == 0) dvs[nl] = (i < n) ? g_dinv[i] : 0.f;
    }
    __syncthreads();

    int c2 = tid & 7, q = tid >> 3;
    __half2 acc[4][8];
    #pragma unroll
    for (int r = 0; r < 4; r++)
        #pragma unroll
        for (int m = 0; m < 8; m++) acc[r][m] = __floats2half2_rn(0.f, 0.f);
    #pragma unroll 4
    for (int k2 = 0; k2 < 32; k2++) {
        __half2 wv[8];
        *(uint4*)&wv[0] = *(const uint4*)&W2h[k2][8 * c2];
        *(uint4*)&wv[4] = *(const uint4*)&W2h[k2][8 * c2 + 4];
        #pragma unroll
        for (int r = 0; r < 4; r++) {
            __half2 h = h1h[q * 4 + r][k2];
            #pragma unroll
            for (int m = 0; m < 8; m++)
                acc[r][m] = __hfma2(h, wv[m], acc[r][m]);
        }
    }
    #pragma unroll
    for (int r = 0; r < 4; r++) {
        int nl = q * 4 + r;
        int i = base + nl;
        if (i < n) {
            float dinv = dvs[nl];
            union { uint4 u; __half2 h[4]; } pk;
            #pragma unroll
            for (int m2 = 0; m2 < 4; m2++) {
                float2 f0 = __half22float2(acc[r][2 * m2]);
                float2 f1 = __half22float2(acc[r][2 * m2 + 1]);
                pk.h[m2] = __floats2half2_rn((f0.x + f0.y) * dinv, (f1.x + f1.y) * dinv);
            }
            ((uint4*)g_hs2H)[(size_t)i * 8 + c2] = pk.u;
        }
    }
}

// layer-2 gather + mean-pool partials (b2 folded at head); exact-cover grid
__global__ void __launch_bounds__(256) k_agg2(int n) {
    __shared__ float bsum[F];
    int tid = threadIdx.x, w = tid >> 5, lane = tid & 31;
    int grp = lane >> 3, c = lane & 7;
    if (tid < F) bsum[tid] = 0.f;
    __syncthreads();

    const uint4* hv = (const uint4*)g_hs2H;
    float2 asum[4] = {{0,0},{0,0},{0,0},{0,0}};
    int i = blockIdx.x * 32 + w * 4 + grp;
    if (i < n) {
        int rs = g_rowtmp[i] + g_boff[i >> 10];
        int d  = g_deg[i];
        __half2 a[4];
        uint4 sv = hv[(size_t)i * 8 + c];
        {   __half2* h = (__half2*)&sv;
            #pragma unroll
            for (int m = 0; m < 4; m++) a[m] = h[m]; }
        gather_node_h(hv, rs, d, c, a);
        float dinv = g_dinv[i];
        #pragma unroll
        for (int m = 0; m < 4; m++) {
            float2 f = __half22float2(a[m]);
            asum[m].x = dinv * f.x;
            asum[m].y = dinv * f.y;
        }
    }
    #pragma unroll
    for (int m = 0; m < 4; m++) {
        asum[m].x += __shfl_xor_sync(0xffffffffu, asum[m].x, 8);
        asum[m].y += __shfl_xor_sync(0xffffffffu, asum[m].y, 8);
        asum[m].x += __shfl_xor_sync(0xffffffffu, asum[m].x, 16);
        asum[m].y += __shfl_xor_sync(0xffffffffu, asum[m].y, 16);
    }
    if (grp == 0) {
        #pragma unroll
        for (int m = 0; m < 4; m++) {
            atomicAdd(&bsum[8 * c + 2 * m],     asum[m].x);
            atomicAdd(&bsum[8 * c + 2 * m + 1], asum[m].y);
        }
    }
    __syncthreads();
    if (tid < F) atomicAdd(&g_gsum[tid], bsum[tid]);
}

// head: g = gsum/n + b2 ; s = relu(state@Wm + bm) ; out = [g,s] @ Wc + bc
__global__ void k_final(const float* __restrict__ state, const float* __restrict__ Wm,
                        const float* __restrict__ bm, const float* __restrict__ Wc,
                        const float* __restrict__ bc, const float* __restrict__ b2,
                        float* __restrict__ out, int n) {
    __shared__ float c128[128];
    int j = threadIdx.x;                           // 128 threads
    if (j < 64) {
        c128[j] = g_gsum[j] / (float)n + b2[j];
    } else {
        int jj = j - 64;
        float s = bm[jj];
        #pragma unroll
        for (int k = 0; k < 8; k++) s += state[k] * Wm[k * 64 + jj];
        c128[j] = fmaxf(s, 0.f);
    }
    __syncthreads();
    if (j < 2) {
        float s = bc[j];
        for (int k = 0; k < 128; k++) s += c128[k] * Wc[k * 2 + j];
        out[j] = s;
    }
}

// ---------------------------------------------------------------------------
extern "C" void kernel_launch(void* const* d_in, const int* in_sizes, int n_in,
                              void* d_out, int out_size) {
    const float* x     = (const float*)d_in[0];
    const float* state = (const float*)d_in[1];
    const float* W1    = (const float*)d_in[2];
    const float* b1    = (const float*)d_in[3];
    const float* W2    = (const float*)d_in[4];
    const float* b2    = (const float*)d_in[5];
    const float* Wm    = (const float*)d_in[6];
    const float* bm    = (const float*)d_in[7];
    const float* Wc    = (const float*)d_in[8];
    const float* bc    = (const float*)d_in[9];
    const int*   ei    = (const int*)d_in[10];
    float* out         = (float*)d_out;

    int n = in_sizes[0] / 8;       // 100000
    int e = in_sizes[10] / 2;      // 1250000
    const int* src = ei;
    const int* dst = ei + e;

    int nb1 = (n + 1023) / 1024;   // 98 <= 128

    void* p_deg = nullptr;
    cudaGetSymbolAddress(&p_deg, g_deg);
    cudaMemsetAsync(p_deg, 0, (size_t)n * sizeof(int));

    const int T = 256;
    k_deg<<<1184, T>>>(dst, e);
    k_scan1_gemm1<<<nb1, 1024>>>(x, W1, n);
    k_scan2<<<1, 128>>>(nb1);
    k_fill<<<1184, T>>>(src, dst, e, nb1);
    k_gather1<<<(n + 31) / 32, T>>>(b1, n);
    k_gemm2<<<(n + 127) / 128, T>>>(W2, n);
    k_agg2<<<(n + 31) / 32, T>>>(n);
    k_final<<<1, 128>>>(state, Wm, bm, Wc, bc, b2, out, n);
}